// round 9
// baseline (speedup 1.0000x reference)
#include <cuda_runtime.h>
#include <cstdint>

// TensorProduct via x2-folded tf32 GEMMs, round 9:
//  - B operands pre-transformed (scaled, tf32, swizzled) into __device__ global
//    scratch by a prep kernel; mainloop reads B frags via LDG (L2-resident,
//    all CTAs share the same 80 KB) -> B leaves the smem crossbar entirely.
//  - A double-buffered in smem; 8 compute warps (mma) overlap with 8 mover
//    warps (stage A for t+1, copy out O of t-1). 2 syncthreads per tile.

#define NTHREADS 512
#define TILE     32

#define RS_AS 136            // 128 + 8 pad (words)
#define RS_AV 200            // 192 + 8 pad
#define RS_O  264            // 256 + 8 pad
#define AS_SZ (TILE * RS_AS)             // 4352
#define AV_SZ (TILE * RS_AV)             // 6400
#define ABUF  (AS_SZ + 3 * AV_SZ)        // 23552 words per A buffer
#define OFF_O (2 * ABUF)                 // 47104
#define SMEM_WORDS (OFF_O + TILE * RS_O) // 55552
#define SMEM_BYTES (SMEM_WORDS * 4)      // 222208 B

__device__ uint32_t g_Bs[64 * 128];      // [w][Kswz]  GEMM_s operand
__device__ uint32_t g_Bv[64 * 192];      // [w][Kswz]  GEMM_v operand (shared by kv)

__device__ __forceinline__ uint32_t tf32c(float f) {
    uint32_t u; asm("cvt.rna.tf32.f32 %0, %1;" : "=r"(u) : "f"(f)); return u;
}
// depth swizzle: element K placed so a thread's {K, K+4} pair is one 8B load
__device__ __forceinline__ int swz(int K) {
    return ((K >> 3) << 3) + ((K & 3) << 1) + ((K >> 2) & 1);
}
__device__ __forceinline__ void mma8(float* c, uint32_t a0, uint32_t a1,
                                     uint32_t a2, uint32_t a3,
                                     uint32_t b0, uint32_t b1) {
    asm volatile(
        "mma.sync.aligned.m16n8k8.row.col.f32.tf32.tf32.f32 "
        "{%0,%1,%2,%3}, {%4,%5,%6,%7}, {%8,%9}, {%0,%1,%2,%3};"
        : "+f"(c[0]), "+f"(c[1]), "+f"(c[2]), "+f"(c[3])
        : "r"(a0), "r"(a1), "r"(a2), "r"(a3), "r"(b0), "r"(b1));
}

// ---------------- prep: build B scratch (runs once per launch) ----------------
__global__ void prep_kernel(const float* __restrict__ w1, const float* __restrict__ w2,
                            const float* __restrict__ w3, const float* __restrict__ w4,
                            const float* __restrict__ w5) {
    const float A0   = 0.08838834764831845f;   // sqrt(1/128)
    const float A0S3 = 0.05103103630798288f;   // a0/sqrt(3)
    const float A1   = 0.07216878364870323f;   // sqrt(1/192)
    const float A1R2 = 0.05103103630798288f;   // a1/sqrt(2)
    int i = blockIdx.x * blockDim.x + threadIdx.x;
    if (i < 64 * 128) {
        int K = i >> 6, w = i & 63;
        float v = (K < 64) ? A0 * w1[K * 64 + w] : A0S3 * w2[(K - 64) * 64 + w];
        g_Bs[w * 128 + swz(K)] = tf32c(v);
    }
    int j = i - 64 * 128;
    if (j >= 0 && j < 64 * 192) {
        int K = j >> 6, w = j & 63;
        float v = (K < 64)  ? A1 * w3[K * 64 + w]
                : (K < 128) ? A1 * w4[(K - 64) * 64 + w]
                :             A1R2 * w5[(K - 128) * 64 + w];
        g_Bv[w * 192 + swz(K)] = tf32c(v);
    }
}

// ---------------- A staging (fold x2 into x1 features) ----------------
__device__ __forceinline__ void stage_A(uint32_t* sm, int dst, int row0, int n,
                                        const float* __restrict__ x1,
                                        const float* __restrict__ x2,
                                        int tsub, int tsz) {
    for (int cell = tsub; cell < TILE * 64; cell += tsz) {
        int r = cell >> 6, u = cell & 63;
        int row = row0 + r;
        float s = 0.f, v0 = 0.f, v1 = 0.f, v2 = 0.f;
        float xs = 0.f, y0 = 0.f, y1 = 0.f, y2 = 0.f;
        if (row < n) {
            const float* xp = x1 + (size_t)row * 256;
            s = xp[u];
            const float* vp = xp + 64 + 3 * u;
            v0 = vp[0]; v1 = vp[1]; v2 = vp[2];
            float4 q = *(const float4*)(x2 + (size_t)row * 4);
            xs = q.x; y0 = q.y; y1 = q.z; y2 = q.w;
        }
        uint32_t* As = sm + dst + r * RS_AS;
        As[swz(u)]      = tf32c(s * xs);
        As[swz(64 + u)] = tf32c(v0 * y0 + v1 * y1 + v2 * y2);
        uint32_t* Av0 = sm + dst + AS_SZ + r * RS_AV;
        Av0[swz(u)]       = tf32c(s * y0);
        Av0[swz(64 + u)]  = tf32c(v0 * xs);
        Av0[swz(128 + u)] = tf32c(v1 * y2 - v2 * y1);
        uint32_t* Av1 = Av0 + AV_SZ;
        Av1[swz(u)]       = tf32c(s * y1);
        Av1[swz(64 + u)]  = tf32c(v1 * xs);
        Av1[swz(128 + u)] = tf32c(v2 * y0 - v0 * y2);
        uint32_t* Av2 = Av1 + AV_SZ;
        Av2[swz(u)]       = tf32c(s * y2);
        Av2[swz(64 + u)]  = tf32c(v2 * xs);
        Av2[swz(128 + u)] = tf32c(v0 * y1 - v1 * y0);
    }
}

// ---------------- mainloop (M32 x N32, KS k-steps, B from global) ------------
template <int KS, int RSA, int BK>
__device__ __forceinline__ void run_mma(const uint32_t* __restrict__ aP,
                                        const uint32_t* __restrict__ bP,
                                        float acc[2][4][4]) {
    uint2 bc[4], bn[4];
    #pragma unroll
    for (int t = 0; t < 4; t++)
        bc[t] = __ldg((const uint2*)(bP + t * 8 * BK));
    #pragma unroll 8
    for (int ks = 0; ks < KS; ks++) {
        if (ks + 1 < KS) {
            #pragma unroll
            for (int t = 0; t < 4; t++)
                bn[t] = __ldg((const uint2*)(bP + t * 8 * BK + (ks + 1) * 8));
        }
        uint2 a0l = *(const uint2*)(aP + ks * 8);
        uint2 a0h = *(const uint2*)(aP + 8 * RSA + ks * 8);
        uint2 a1l = *(const uint2*)(aP + 16 * RSA + ks * 8);
        uint2 a1h = *(const uint2*)(aP + 24 * RSA + ks * 8);
        #pragma unroll
        for (int t = 0; t < 4; t++) {
            mma8(acc[0][t], a0l.x, a0h.x, a0l.y, a0h.y, bc[t].x, bc[t].y);
            mma8(acc[1][t], a1l.x, a1h.x, a1l.y, a1h.y, bc[t].x, bc[t].y);
        }
        #pragma unroll
        for (int t = 0; t < 4; t++) bc[t] = bn[t];
    }
}

__global__ __launch_bounds__(NTHREADS, 1)
void tp_mma2_kernel(const float* __restrict__ x1, const float* __restrict__ x2,
                    float* __restrict__ out, int n) {
    extern __shared__ uint32_t sm[];
    float* osm = (float*)(sm + OFF_O);
    const int tid  = threadIdx.x;
    const int lane = tid & 31;
    const int wid  = tid >> 5;
    const bool isCompute = (wid < 8);
    const bool isS = (wid < 2);

    // compute-warp geometry
    int kv = 0, half;
    if (isS) half = wid;
    else { kv = (wid - 2) >> 1; half = (wid - 2) & 1; }
    const int wbase = half * 32;
    const int aOffLocal = isS ? 0 : (AS_SZ + kv * AV_SZ);
    const int rsA = isS ? RS_AS : RS_AV;
    const uint32_t* bP = (isS ? g_Bs : g_Bv)
                       + (wbase + (lane >> 2)) * (isS ? 128 : 192)
                       + (lane & 3) * 2;
    const int mtid = tid - 256;   // mover thread id (wid >= 8)

    const int numTiles = (n + TILE - 1) / TILE;

    // prologue: everyone stages tile #blockIdx.x into buffer 0
    stage_A(sm, 0, blockIdx.x * TILE, n, x1, x2, tid, NTHREADS);
    __syncthreads();

    int i = 0;
    int tile = blockIdx.x;
    for (; tile < numTiles; tile += gridDim.x, i++) {
        const int p = i & 1;

        if (isCompute) {
            float acc[2][4][4];
            #pragma unroll
            for (int s2 = 0; s2 < 2; s2++)
                #pragma unroll
                for (int t = 0; t < 4; t++)
                    #pragma unroll
                    for (int c = 0; c < 4; c++) acc[s2][t][c] = 0.f;

            const uint32_t* aP = sm + p * ABUF + aOffLocal
                               + (lane >> 2) * rsA + (lane & 3) * 2;
            if (isS) run_mma<16, RS_AS, 128>(aP, bP, acc);
            else     run_mma<24, RS_AV, 192>(aP, bP, acc);

            __syncthreads();   // W1 end: movers done with O(t-1) + A[1-p] staged

            // scatter acc -> osm
            #pragma unroll
            for (int s2 = 0; s2 < 2; s2++) {
                int r1 = s2 * 16 + (lane >> 2);
                if (isS) {
                    #pragma unroll
                    for (int t = 0; t < 4; t++) {
                        int w = wbase + t * 8 + ((lane & 3) << 1);
                        *(float2*)&osm[r1 * RS_O + w] =
                            make_float2(acc[s2][t][0], acc[s2][t][1]);
                        *(float2*)&osm[(r1 + 8) * RS_O + w] =
                            make_float2(acc[s2][t][2], acc[s2][t][3]);
                    }
                } else {
                    #pragma unroll
                    for (int t = 0; t < 4; t++) {
                        int w = wbase + t * 8 + ((lane & 3) << 1);
                        osm[r1 * RS_O + 64 + 3 * w + kv]             = acc[s2][t][0];
                        osm[r1 * RS_O + 64 + 3 * (w + 1) + kv]       = acc[s2][t][1];
                        osm[(r1 + 8) * RS_O + 64 + 3 * w + kv]       = acc[s2][t][2];
                        osm[(r1 + 8) * RS_O + 64 + 3 * (w + 1) + kv] = acc[s2][t][3];
                    }
                }
            }
        } else {
            // movers: copy out O of tile t-gridDim.x, then stage A for t+gridDim.x
            if (i > 0) {
                int prow0 = (tile - gridDim.x) * TILE;
                #pragma unroll 8
                for (int idx = mtid; idx < TILE * 64; idx += 256) {
                    int r = idx >> 6, c4 = (idx & 63) << 2;
                    int row = prow0 + r;
                    if (row < n)
                        *(float4*)(out + (size_t)row * 256 + c4) =
                            *(const float4*)(osm + r * RS_O + c4);
                }
            }
            int ntile = tile + gridDim.x;
            if (ntile < numTiles)
                stage_A(sm, (1 - p) * ABUF, ntile * TILE, n, x1, x2, mtid, 256);
            __syncthreads();   // W1 end
        }
        __syncthreads();       // W2 end: scatter complete
    }

    // epilogue: copy out the last tile this CTA processed
    if (i > 0) {
        int lrow0 = (tile - gridDim.x) * TILE;
        #pragma unroll 4
        for (int idx = tid; idx < TILE * 64; idx += NTHREADS) {
            int r = idx >> 6, c4 = (idx & 63) << 2;
            int row = lrow0 + r;
            if (row < n)
                *(float4*)(out + (size_t)row * 256 + c4) =
                    *(const float4*)(osm + r * RS_O + c4);
        }
    }
}

extern "C" void kernel_launch(void* const* d_in, const int* in_sizes, int n_in,
                              void* d_out, int out_size) {
    const float* x1 = (const float*)d_in[0];
    const float* x2 = (const float*)d_in[1];
    const float* w1 = (const float*)d_in[2];   // w_ss_s
    const float* w2 = (const float*)d_in[3];   // w_vv_s
    const float* w3 = (const float*)d_in[4];   // w_sv_v
    const float* w4 = (const float*)d_in[5];   // w_vs_v
    const float* w5 = (const float*)d_in[6];   // w_vv_v
    float* out = (float*)d_out;

    int n = in_sizes[0] / 256;
    prep_kernel<<<40, 512>>>(w1, w2, w3, w4, w5);

    cudaFuncSetAttribute(tp_mma2_kernel,
                         cudaFuncAttributeMaxDynamicSharedMemorySize, SMEM_BYTES);
    tp_mma2_kernel<<<148, NTHREADS, SMEM_BYTES>>>(x1, x2, out, n);
}

// round 11
// speedup vs baseline: 1.3551x; 1.3551x over previous
#include <cuda_runtime.h>
#include <cstdint>

// TensorProduct, round 11: unfolded tf32 mma.sync formulation.
//   Y1  = x1s  @ [a0*W1 | a1*W3]              (K=64, N=128)
//   Y2k = x1vk @ [a0/s3*W2 | a1*W4 | a1/s2*W5] (K=64, N=192; B shared over k)
// Epilogue per row combines with x2 (dot, scalar muls, cross product) fully
// in-register thanks to a per-thread-aligned B column permutation.
// 32-row tiles, 8 warps (M16 x 16w x 4 GEMMs each), cp.async x1 pipeline.

#define NTH   256
#define TILE  32
#define RS    68      // K-row stride (words): 4r+2q bank-optimal, 8B aligned
#define RS_O  260

#define OFF_RAW0 0
#define OFF_RAW1 8192
#define OFF_AS   16384
#define OFF_AV0  (OFF_AS  + TILE * RS)
#define OFF_AV1  (OFF_AV0 + TILE * RS)
#define OFF_AV2  (OFF_AV1 + TILE * RS)
#define OFF_B1   (OFF_AV2 + TILE * RS)     // 128 rows
#define OFF_B2   (OFF_B1 + 128 * RS)       // 192 rows
#define OFF_OSM  (OFF_B2 + 192 * RS)
#define SMEM_WORDS (OFF_OSM + TILE * RS_O)
#define SMEM_BYTES (SMEM_WORDS * 4)        // 220672

__device__ __forceinline__ uint32_t tf32c(float f) {
    uint32_t u; asm("cvt.rna.tf32.f32 %0, %1;" : "=r"(u) : "f"(f)); return u;
}
// place K so a thread's {k, k+4} pair is one aligned 8B load
__device__ __forceinline__ int swz(int K) {
    return ((K >> 3) << 3) + ((K & 3) << 1) + ((K >> 2) & 1);
}
__device__ __forceinline__ uint32_t smem_u32(const void* p) {
    uint32_t a;
    asm("{ .reg .u64 t; cvta.to.shared.u64 t, %1; cvt.u32.u64 %0, t; }"
        : "=r"(a) : "l"(p));
    return a;
}
__device__ __forceinline__ void mma8(float* c, uint32_t a0, uint32_t a1,
                                     uint32_t a2, uint32_t a3,
                                     uint32_t b0, uint32_t b1) {
    asm volatile(
        "mma.sync.aligned.m16n8k8.row.col.f32.tf32.tf32.f32 "
        "{%0,%1,%2,%3}, {%4,%5,%6,%7}, {%8,%9}, {%0,%1,%2,%3};"
        : "+f"(c[0]), "+f"(c[1]), "+f"(c[2]), "+f"(c[3])
        : "r"(a0), "r"(a1), "r"(a2), "r"(a3), "r"(b0), "r"(b1));
}
__device__ __forceinline__ void cpa16(uint32_t dst, const void* src) {
    asm volatile("cp.async.cg.shared.global [%0], [%1], 16;"
                 :: "r"(dst), "l"(src));
}

__global__ __launch_bounds__(NTH, 1)
void tp_k(const float* __restrict__ x1, const float* __restrict__ x2,
          const float* __restrict__ w1, const float* __restrict__ w2,
          const float* __restrict__ w3, const float* __restrict__ w4,
          const float* __restrict__ w5,
          float* __restrict__ out, int n) {
    extern __shared__ uint32_t sw[];
    const int tid  = threadIdx.x;
    const int lane = tid & 31;
    const int wid  = tid >> 5;
    const int q    = lane & 3;
    const int rsub = lane >> 2;          // 0..7
    const int slab = wid >> 2;           // 0..1  (rows slab*16)
    const int qd   = wid & 3;            // w-quarter: w in [16qd, 16qd+16)

    const float A0   = 0.08838834764831845f;   // sqrt(1/128)
    const float A0S3 = 0.05103103630798288f;   // a0/sqrt(3)
    const float A1   = 0.07216878364870323f;   // sqrt(1/192)
    const float A1R2 = 0.05103103630798288f;   // a1/sqrt(2)

    const int numTiles = (n + TILE - 1) / TILE;
    const uint32_t sbRaw0 = smem_u32(sw + OFF_RAW0);
    const uint32_t sbRaw1 = smem_u32(sw + OFF_RAW1);

    // ---- prologue: cp.async first tile into raw0 ----
    if (blockIdx.x < numTiles) {
        int row0 = blockIdx.x * TILE;
        #pragma unroll
        for (int it = 0; it < 8; it++) {
            int idx = tid + it * NTH;               // 2048 16B chunks
            int r = idx >> 6, c = (idx & 63) << 2;
            int grow = row0 + r; if (grow >= n) grow = 0;
            cpa16(sbRaw0 + (idx << 4), x1 + (size_t)grow * 256 + c);
        }
    }
    asm volatile("cp.async.commit_group;" ::: "memory");

    // ---- stage B with per-thread-aligned column permutation ----
    // B1: n = 32*qd' + 8*w' + 2*q' + m   (m=0 -> a0*W1 (y1), m=1 -> a1*W3 (y3))
    for (int i = tid; i < 128 * 64; i += NTH) {
        int nn = i >> 6, k = i & 63;
        int qdd = nn >> 5, nl = nn & 31;
        int wp = nl >> 3, rem = nl & 7, qq = rem >> 1, m = rem & 1;
        int w = 16 * qdd + 4 * qq + wp;
        float v = m ? A1 * w3[k * 64 + w] : A0 * w1[k * 64 + w];
        sw[OFF_B1 + nn * RS + swz(k)] = tf32c(v);
    }
    // B2: n = 48*qd' + 8*t + 2*q' + j ; s=2t+j; w'=s/3; m=s%3
    //     (m=0 -> a0/s3*W2 (y2), m=1 -> a1*W4 (y4), m=2 -> a1/s2*W5 (y5))
    for (int i = tid; i < 192 * 64; i += NTH) {
        int nn = i >> 6, k = i & 63;
        int qdd = nn / 48, nl = nn - 48 * qdd;
        int t = nl >> 3, rem = nl & 7, qq = rem >> 1, j = rem & 1;
        int s = 2 * t + j, wp = s / 3, m = s - 3 * wp;
        int w = 16 * qdd + 4 * qq + wp;
        float v = (m == 0) ? A0S3 * w2[k * 64 + w]
                : (m == 1) ? A1 * w4[k * 64 + w]
                :            A1R2 * w5[k * 64 + w];
        sw[OFF_B2 + nn * RS + swz(k)] = tf32c(v);
    }
    asm volatile("cp.async.wait_group 0;" ::: "memory");
    __syncthreads();

    float* osm = (float*)(sw + OFF_OSM);
    const int rl0 = slab * 16 + rsub;
    const int wb  = 16 * qd + 4 * q;

    int it8 = 0;
    for (int tile = blockIdx.x; tile < numTiles; tile += gridDim.x, it8++) {
        const int p = it8 & 1;
        const int row0 = tile * TILE;

        // ---- phase A: issue next-tile cp.async, prefetch x2, repack A ----
        int ntile = tile + gridDim.x;
        if (ntile < numTiles) {
            int nrow0 = ntile * TILE;
            uint32_t dstB = p ? sbRaw0 : sbRaw1;
            #pragma unroll
            for (int it = 0; it < 8; it++) {
                int idx = tid + it * NTH;
                int r = idx >> 6, c = (idx & 63) << 2;
                int grow = nrow0 + r; if (grow >= n) grow = 0;
                cpa16(dstB + (idx << 4), x1 + (size_t)grow * 256 + c);
            }
        }
        asm volatile("cp.async.commit_group;" ::: "memory");

        float4 xq0 = make_float4(0.f, 0.f, 0.f, 0.f), xq1 = xq0;
        if (row0 + rl0 < n)     xq0 = *(const float4*)(x2 + (size_t)(row0 + rl0) * 4);
        if (row0 + rl0 + 8 < n) xq1 = *(const float4*)(x2 + (size_t)(row0 + rl0 + 8) * 4);

        const float* rawf = (const float*)(sw + (p ? OFF_RAW1 : OFF_RAW0));
        #pragma unroll
        for (int it = 0; it < 8; it++) {
            int cell = tid + it * NTH;               // 2048 = 32 rows x 64 u
            int r = cell >> 6, u = cell & 63;
            float s  = rawf[r * 256 + u];
            float v0 = rawf[r * 256 + 64 + 3 * u];
            float v1 = rawf[r * 256 + 64 + 3 * u + 1];
            float v2 = rawf[r * 256 + 64 + 3 * u + 2];
            int ao = r * RS + swz(u);
            sw[OFF_AS  + ao] = tf32c(s);
            sw[OFF_AV0 + ao] = tf32c(v0);
            sw[OFF_AV1 + ao] = tf32c(v1);
            sw[OFF_AV2 + ao] = tf32c(v2);
        }
        __syncthreads();

        // ---- phase B: mainloop (K=64 -> 8 k-steps, 22 mma each) ----
        float acc1[4][4];
        float acc2[3][6][4];
        #pragma unroll
        for (int t = 0; t < 4; t++)
            #pragma unroll
            for (int c = 0; c < 4; c++) acc1[t][c] = 0.f;
        #pragma unroll
        for (int kv = 0; kv < 3; kv++)
            #pragma unroll
            for (int t = 0; t < 6; t++)
                #pragma unroll
                for (int c = 0; c < 4; c++) acc2[kv][t][c] = 0.f;

        const uint32_t* aS = sw + OFF_AS + (slab * 16 + rsub) * RS + q * 2;
        const uint32_t* b1 = sw + OFF_B1 + (32 * qd + rsub) * RS + q * 2;
        const uint32_t* b2 = sw + OFF_B2 + (48 * qd + rsub) * RS + q * 2;

        #pragma unroll
        for (int ks = 0; ks < 8; ks++) {
            uint2 sl = *(const uint2*)(aS + ks * 8);
            uint2 sh = *(const uint2*)(aS + 8 * RS + ks * 8);
            uint2 vl[3], vh[3];
            #pragma unroll
            for (int kv = 0; kv < 3; kv++) {
                vl[kv] = *(const uint2*)(aS + (kv + 1) * TILE * RS + ks * 8);
                vh[kv] = *(const uint2*)(aS + (kv + 1) * TILE * RS + 8 * RS + ks * 8);
            }
            #pragma unroll
            for (int t = 0; t < 4; t++) {
                uint2 b = *(const uint2*)(b1 + t * 8 * RS + ks * 8);
                mma8(acc1[t], sl.x, sh.x, sl.y, sh.y, b.x, b.y);
            }
            #pragma unroll
            for (int t = 0; t < 6; t++) {
                uint2 b = *(const uint2*)(b2 + t * 8 * RS + ks * 8);
                mma8(acc2[0][t], vl[0].x, vh[0].x, vl[0].y, vh[0].y, b.x, b.y);
                mma8(acc2[1][t], vl[1].x, vh[1].x, vl[1].y, vh[1].y, b.x, b.y);
                mma8(acc2[2][t], vl[2].x, vh[2].x, vl[2].y, vh[2].y, b.x, b.y);
            }
        }

        // ---- epilogue: in-register combine with x2, write osm ----
        #pragma unroll
        for (int p2 = 0; p2 < 2; p2++) {
            int rl = rl0 + 8 * p2;
            float xs  = p2 ? xq1.x : xq0.x;
            float xv0 = p2 ? xq1.y : xq0.y;
            float xv1 = p2 ? xq1.z : xq0.z;
            float xv2 = p2 ? xq1.w : xq0.w;
            float os4[4], ov[12];
            #pragma unroll
            for (int wp = 0; wp < 4; wp++) {
                float y1 = acc1[wp][2 * p2 + 0];
                float y3 = acc1[wp][2 * p2 + 1];
                int s0 = 3 * wp,     t0 = s0 >> 1, j0 = s0 & 1;
                int s1 = 3 * wp + 1, t1 = s1 >> 1, j1 = s1 & 1;
                int s2 = 3 * wp + 2, t2 = s2 >> 1, j2 = s2 & 1;
                float y2a = acc2[0][t0][2 * p2 + j0];
                float y2b = acc2[1][t0][2 * p2 + j0];
                float y2c = acc2[2][t0][2 * p2 + j0];
                float y4a = acc2[0][t1][2 * p2 + j1];
                float y4b = acc2[1][t1][2 * p2 + j1];
                float y4c = acc2[2][t1][2 * p2 + j1];
                float y5a = acc2[0][t2][2 * p2 + j2];
                float y5b = acc2[1][t2][2 * p2 + j2];
                float y5c = acc2[2][t2][2 * p2 + j2];

                os4[wp] = xs * y1 + xv0 * y2a + xv1 * y2b + xv2 * y2c;
                ov[3 * wp + 0] = xv0 * y3 + xs * y4a + (y5b * xv2 - y5c * xv1);
                ov[3 * wp + 1] = xv1 * y3 + xs * y4b + (y5c * xv0 - y5a * xv2);
                ov[3 * wp + 2] = xv2 * y3 + xs * y4c + (y5a * xv1 - y5b * xv0);
            }
            *(float4*)&osm[rl * RS_O + wb] =
                make_float4(os4[0], os4[1], os4[2], os4[3]);
            *(float4*)&osm[rl * RS_O + 64 + 3 * wb + 0] =
                make_float4(ov[0], ov[1], ov[2], ov[3]);
            *(float4*)&osm[rl * RS_O + 64 + 3 * wb + 4] =
                make_float4(ov[4], ov[5], ov[6], ov[7]);
            *(float4*)&osm[rl * RS_O + 64 + 3 * wb + 8] =
                make_float4(ov[8], ov[9], ov[10], ov[11]);
        }
        __syncthreads();

        // ---- phase C: coalesced osm -> out, then wait next raw ----
        #pragma unroll
        for (int it = 0; it < 8; it++) {
            int idx = tid + it * NTH;
            int r = idx >> 6, c = (idx & 63) << 2;
            int grow = row0 + r;
            if (grow < n)
                *(float4*)(out + (size_t)grow * 256 + c) =
                    *(const float4*)(osm + r * RS_O + c);
        }
        asm volatile("cp.async.wait_group 0;" ::: "memory");
        __syncthreads();
    }
}

extern "C" void kernel_launch(void* const* d_in, const int* in_sizes, int n_in,
                              void* d_out, int out_size) {
    const float* x1 = (const float*)d_in[0];
    const float* x2 = (const float*)d_in[1];
    const float* w1 = (const float*)d_in[2];   // w_ss_s
    const float* w2 = (const float*)d_in[3];   // w_vv_s
    const float* w3 = (const float*)d_in[4];   // w_sv_v
    const float* w4 = (const float*)d_in[5];   // w_vs_v
    const float* w5 = (const float*)d_in[6];   // w_vv_v
    float* out = (float*)d_out;

    int n = in_sizes[0] / 256;
    cudaFuncSetAttribute(tp_k, cudaFuncAttributeMaxDynamicSharedMemorySize,
                         SMEM_BYTES);
    int numTiles = (n + TILE - 1) / TILE;
    int grid = numTiles < 148 ? numTiles : 148;
    tp_k<<<grid, NTH, SMEM_BYTES>>>(x1, x2, w1, w2, w3, w4, w5, out, n);
}

// round 12
// speedup vs baseline: 1.5061x; 1.1114x over previous
#include <cuda_runtime.h>
#include <cstdint>

// TensorProduct, round 12: unfolded tf32 mma.sync, 12 warps, direct-STG epilogue.
//   Y1  = x1s  @ [a0*W1 | a1*W3]               (K=64, N=128)
//   Y2k = x1vk @ [a0/s3*W2 | a1*W4 | a1/s2*W5]  (K=64, N=192; B shared over k)
// 48-row tiles, 12 warps = 3 row-slabs x 4 w-quarters, M16x16w each.
// Epilogue combines with x2 in-register (incl. cross product) and stores
// float4 runs straight to global (no smem restage). Single raw x1 buffer,
// cp.async for tile t+1 issued right after tile t's repack frees it.

#define NTH   384
#define TILE  48
#define RS    68      // K-row stride in words (bank-staggered, 8B aligned)

#define OFF_RAW  0
#define RAW_WORDS (TILE * 256)                  // 12288
#define PLANE    (TILE * RS)                    // 3264
#define OFF_AS   RAW_WORDS
#define OFF_B1   (OFF_AS + 4 * PLANE)           // 25344
#define OFF_B2   (OFF_B1 + 128 * RS)            // 34048
#define SMEM_WORDS (OFF_B2 + 192 * RS)          // 47104
#define SMEM_BYTES (SMEM_WORDS * 4)             // 188416

__device__ __forceinline__ uint32_t tf32c(float f) {
    uint32_t u; asm("cvt.rna.tf32.f32 %0, %1;" : "=r"(u) : "f"(f)); return u;
}
// place K so a thread's {k, k+4} pair is one aligned 8B load
__device__ __forceinline__ int swz(int K) {
    return ((K >> 3) << 3) + ((K & 3) << 1) + ((K >> 2) & 1);
}
__device__ __forceinline__ uint32_t smem_u32(const void* p) {
    uint32_t a;
    asm("{ .reg .u64 t; cvta.to.shared.u64 t, %1; cvt.u32.u64 %0, t; }"
        : "=r"(a) : "l"(p));
    return a;
}
__device__ __forceinline__ void mma8(float* c, uint32_t a0, uint32_t a1,
                                     uint32_t a2, uint32_t a3,
                                     uint32_t b0, uint32_t b1) {
    asm volatile(
        "mma.sync.aligned.m16n8k8.row.col.f32.tf32.tf32.f32 "
        "{%0,%1,%2,%3}, {%4,%5,%6,%7}, {%8,%9}, {%0,%1,%2,%3};"
        : "+f"(c[0]), "+f"(c[1]), "+f"(c[2]), "+f"(c[3])
        : "r"(a0), "r"(a1), "r"(a2), "r"(a3), "r"(b0), "r"(b1));
}
__device__ __forceinline__ void cpa16(uint32_t dst, const void* src) {
    asm volatile("cp.async.cg.shared.global [%0], [%1], 16;"
                 :: "r"(dst), "l"(src));
}

__global__ __launch_bounds__(NTH, 1)
void tp_k(const float* __restrict__ x1, const float* __restrict__ x2,
          const float* __restrict__ w1, const float* __restrict__ w2,
          const float* __restrict__ w3, const float* __restrict__ w4,
          const float* __restrict__ w5,
          float* __restrict__ out, int n) {
    extern __shared__ uint32_t sw[];
    const int tid  = threadIdx.x;
    const int lane = tid & 31;
    const int wid  = tid >> 5;
    const int q    = lane & 3;
    const int rsub = lane >> 2;          // 0..7
    const int slab = wid >> 2;           // 0..2  (rows slab*16)
    const int qd   = wid & 3;            // w-quarter: w in [16qd, 16qd+16)

    const float A0   = 0.08838834764831845f;   // sqrt(1/128)
    const float A0S3 = 0.05103103630798288f;   // a0/sqrt(3)
    const float A1   = 0.07216878364870323f;   // sqrt(1/192)
    const float A1R2 = 0.05103103630798288f;   // a1/sqrt(2)

    const int numTiles = (n + TILE - 1) / TILE;
    const uint32_t sbRaw = smem_u32(sw + OFF_RAW);

    // ---- prologue: cp.async first tile into raw ----
    {
        int row0 = blockIdx.x * TILE;
        #pragma unroll
        for (int it = 0; it < 8; it++) {
            int idx = tid + it * NTH;               // 3072 16B chunks
            int r = idx >> 6, c = (idx & 63) << 2;
            int grow = row0 + r; if (grow >= n) grow = 0;
            cpa16(sbRaw + (idx << 4), x1 + (size_t)grow * 256 + c);
        }
    }
    asm volatile("cp.async.commit_group;" ::: "memory");

    // ---- stage B with per-thread-aligned column permutation ----
    // B1: n = 32*qd' + 8*w' + 2*q' + m   (m=0 -> a0*W1 (y1), m=1 -> a1*W3 (y3))
    for (int i = tid; i < 128 * 64; i += NTH) {
        int nn = i >> 6, k = i & 63;
        int qdd = nn >> 5, nl = nn & 31;
        int wp = nl >> 3, rem = nl & 7, qq = rem >> 1, m = rem & 1;
        int w = 16 * qdd + 4 * qq + wp;
        float v = m ? A1 * w3[k * 64 + w] : A0 * w1[k * 64 + w];
        sw[OFF_B1 + nn * RS + swz(k)] = tf32c(v);
    }
    // B2: n = 48*qd' + 8*t + 2*q' + j ; s=2t+j; w'=s/3; m=s%3
    for (int i = tid; i < 192 * 64; i += NTH) {
        int nn = i >> 6, k = i & 63;
        int qdd = nn / 48, nl = nn - 48 * qdd;
        int t = nl >> 3, rem = nl & 7, qq = rem >> 1, j = rem & 1;
        int s = 2 * t + j, wp = s / 3, m = s - 3 * wp;
        int w = 16 * qdd + 4 * qq + wp;
        float v = (m == 0) ? A0S3 * w2[k * 64 + w]
                : (m == 1) ? A1 * w4[k * 64 + w]
                :            A1R2 * w5[k * 64 + w];
        sw[OFF_B2 + nn * RS + swz(k)] = tf32c(v);
    }

    const int rl0 = slab * 16 + rsub;
    const int wb  = 16 * qd + 4 * q;
    const uint32_t* aS = sw + OFF_AS + rl0 * RS + q * 2;
    const uint32_t* b1 = sw + OFF_B1 + (32 * qd + rsub) * RS + q * 2;
    const uint32_t* b2 = sw + OFF_B2 + (48 * qd + rsub) * RS + q * 2;
    const float* rawf = (const float*)(sw + OFF_RAW);

    for (int tile = blockIdx.x; tile < numTiles; tile += gridDim.x) {
        const int row0 = tile * TILE;

        // ---- wait raw, repack A into tf32 planes; prefetch x2 ----
        asm volatile("cp.async.wait_group 0;" ::: "memory");
        __syncthreads();

        float4 xq0 = make_float4(0.f, 0.f, 0.f, 0.f), xq1 = xq0;
        if (row0 + rl0 < n)     xq0 = *(const float4*)(x2 + (size_t)(row0 + rl0) * 4);
        if (row0 + rl0 + 8 < n) xq1 = *(const float4*)(x2 + (size_t)(row0 + rl0 + 8) * 4);

        #pragma unroll
        for (int it = 0; it < 8; it++) {
            int cell = tid + it * NTH;               // 3072 = 48 rows x 64 u
            int r = cell >> 6, u = cell & 63;
            float s  = rawf[r * 256 + u];
            float v0 = rawf[r * 256 + 64 + 3 * u];
            float v1 = rawf[r * 256 + 64 + 3 * u + 1];
            float v2 = rawf[r * 256 + 64 + 3 * u + 2];
            int ao = r * RS + swz(u);
            sw[OFF_AS + 0 * PLANE + ao] = tf32c(s);
            sw[OFF_AS + 1 * PLANE + ao] = tf32c(v0);
            sw[OFF_AS + 2 * PLANE + ao] = tf32c(v1);
            sw[OFF_AS + 3 * PLANE + ao] = tf32c(v2);
        }
        __syncthreads();   // planes ready; raw free

        // ---- issue next tile's cp.async (hidden under mainloop) ----
        int ntile = tile + gridDim.x;
        if (ntile < numTiles) {
            int nrow0 = ntile * TILE;
            #pragma unroll
            for (int it = 0; it < 8; it++) {
                int idx = tid + it * NTH;
                int r = idx >> 6, c = (idx & 63) << 2;
                int grow = nrow0 + r; if (grow >= n) grow = 0;
                cpa16(sbRaw + (idx << 4), x1 + (size_t)grow * 256 + c);
            }
        }
        asm volatile("cp.async.commit_group;" ::: "memory");

        // ---- mainloop: K=64 -> 8 k-steps, 22 mma each ----
        float acc1[4][4];
        float acc2[3][6][4];
        #pragma unroll
        for (int t = 0; t < 4; t++)
            #pragma unroll
            for (int c = 0; c < 4; c++) acc1[t][c] = 0.f;
        #pragma unroll
        for (int kv = 0; kv < 3; kv++)
            #pragma unroll
            for (int t = 0; t < 6; t++)
                #pragma unroll
                for (int c = 0; c < 4; c++) acc2[kv][t][c] = 0.f;

        #pragma unroll
        for (int ks = 0; ks < 8; ks++) {
            uint2 sl = *(const uint2*)(aS + ks * 8);
            uint2 sh = *(const uint2*)(aS + 8 * RS + ks * 8);
            uint2 vl[3], vh[3];
            #pragma unroll
            for (int kv = 0; kv < 3; kv++) {
                vl[kv] = *(const uint2*)(aS + (kv + 1) * PLANE + ks * 8);
                vh[kv] = *(const uint2*)(aS + (kv + 1) * PLANE + 8 * RS + ks * 8);
            }
            #pragma unroll
            for (int t = 0; t < 4; t++) {
                uint2 b = *(const uint2*)(b1 + t * 8 * RS + ks * 8);
                mma8(acc1[t], sl.x, sh.x, sl.y, sh.y, b.x, b.y);
            }
            #pragma unroll
            for (int t = 0; t < 6; t++) {
                uint2 b = *(const uint2*)(b2 + t * 8 * RS + ks * 8);
                mma8(acc2[0][t], vl[0].x, vh[0].x, vl[0].y, vh[0].y, b.x, b.y);
                mma8(acc2[1][t], vl[1].x, vh[1].x, vl[1].y, vh[1].y, b.x, b.y);
                mma8(acc2[2][t], vl[2].x, vh[2].x, vl[2].y, vh[2].y, b.x, b.y);
            }
        }

        // ---- epilogue: combine with x2 in-register, STG.128 direct ----
        #pragma unroll
        for (int p2 = 0; p2 < 2; p2++) {
            int grow = row0 + rl0 + 8 * p2;
            if (grow >= n) continue;
            float xs  = p2 ? xq1.x : xq0.x;
            float xv0 = p2 ? xq1.y : xq0.y;
            float xv1 = p2 ? xq1.z : xq0.z;
            float xv2 = p2 ? xq1.w : xq0.w;
            float os4[4], ov[12];
            #pragma unroll
            for (int wp = 0; wp < 4; wp++) {
                float y1 = acc1[wp][2 * p2 + 0];
                float y3 = acc1[wp][2 * p2 + 1];
                int s0 = 3 * wp,     t0 = s0 >> 1, j0 = s0 & 1;
                int s1 = 3 * wp + 1, t1 = s1 >> 1, j1 = s1 & 1;
                int s2 = 3 * wp + 2, t2 = s2 >> 1, j2 = s2 & 1;
                float y2a = acc2[0][t0][2 * p2 + j0];
                float y2b = acc2[1][t0][2 * p2 + j0];
                float y2c = acc2[2][t0][2 * p2 + j0];
                float y4a = acc2[0][t1][2 * p2 + j1];
                float y4b = acc2[1][t1][2 * p2 + j1];
                float y4c = acc2[2][t1][2 * p2 + j1];
                float y5a = acc2[0][t2][2 * p2 + j2];
                float y5b = acc2[1][t2][2 * p2 + j2];
                float y5c = acc2[2][t2][2 * p2 + j2];

                os4[wp] = xs * y1 + xv0 * y2a + xv1 * y2b + xv2 * y2c;
                ov[3 * wp + 0] = xv0 * y3 + xs * y4a + (y5b * xv2 - y5c * xv1);
                ov[3 * wp + 1] = xv1 * y3 + xs * y4b + (y5c * xv0 - y5a * xv2);
                ov[3 * wp + 2] = xv2 * y3 + xs * y4c + (y5a * xv1 - y5b * xv0);
            }
            float* orow = out + (size_t)grow * 256;
            *(float4*)(orow + wb) = make_float4(os4[0], os4[1], os4[2], os4[3]);
            *(float4*)(orow + 64 + 3 * wb + 0) =
                make_float4(ov[0], ov[1], ov[2], ov[3]);
            *(float4*)(orow + 64 + 3 * wb + 4) =
                make_float4(ov[4], ov[5], ov[6], ov[7]);
            *(float4*)(orow + 64 + 3 * wb + 8) =
                make_float4(ov[8], ov[9], ov[10], ov[11]);
        }
    }
}

extern "C" void kernel_launch(void* const* d_in, const int* in_sizes, int n_in,
                              void* d_out, int out_size) {
    const float* x1 = (const float*)d_in[0];
    const float* x2 = (const float*)d_in[1];
    const float* w1 = (const float*)d_in[2];   // w_ss_s
    const float* w2 = (const float*)d_in[3];   // w_vv_s
    const float* w3 = (const float*)d_in[4];   // w_sv_v
    const float* w4 = (const float*)d_in[5];   // w_vs_v
    const float* w5 = (const float*)d_in[6];   // w_vv_v
    float* out = (float*)d_out;

    int n = in_sizes[0] / 256;
    cudaFuncSetAttribute(tp_k, cudaFuncAttributeMaxDynamicSharedMemorySize,
                         SMEM_BYTES);
    int numTiles = (n + TILE - 1) / TILE;
    int grid = numTiles < 148 ? numTiles : 148;
    tp_k<<<grid, NTH, SMEM_BYTES>>>(x1, x2, w1, w2, w3, w4, w5, out, n);
}